// round 1
// baseline (speedup 1.0000x reference)
#include <cuda_runtime.h>

// VariantCoeLinear1d: 1D Rusanov/local-Lax-Friedrichs FV solver.
// u^{s+1}[j] = u[j] - (dt/dx) * (fh[j+1/2] - fh[j-1/2]),
// fh = 0.5*(f_l+f_r) - 0.5*max(|f'(u_l)|,|f'(u_r)|)*(u_r-u_l)
// Outflow BC: u[0]=u[1], u[N-1]=u[N-2] (post-update).
//
// Layout: one CTA per batch row (128 CTAs, single wave on 148 SMs).
// Each of 256 threads owns 8 contiguous points in REGISTERS across all
// 255 steps. Per step, each thread exchanges only its boundary
// (u, f, |f'|) triples via double-buffered SMEM halo arrays ->
// exactly one __syncthreads() per step. Frames written with streaming
// float4 stores (write-only data, evict-first).

#define BATCH 128
#define NPTS  2048
#define STEPS 256
#define TPB   256
#define PPT   8   // points per thread (TPB*PPT == NPTS)

static __device__ __forceinline__ void flux_and_speed(float u, float& f, float& a) {
    // f(u)  = 0.5*u*(3-u^2) + (beta/12)*u^2*(0.75 - 2u + 1.5u^2 - 0.25u^4)
    // f'(u) = 1.5*(1-u^2)   + (beta/12)*(1.5u - 6u^2 + 6u^3 - 1.5u^5)
    const float c = 8.333333333333333e-3f;  // beta/12, beta=0.1
    float u2 = u * u;
    float u3 = u2 * u;
    float u4 = u2 * u2;
    float u5 = u2 * u3;
    float t  = fmaf(-0.25f, u4, fmaf(1.5f, u2, fmaf(-2.0f, u, 0.75f)));
    f        = fmaf(c * u2, t, 0.5f * u * (3.0f - u2));
    float q  = fmaf(-1.5f, u5, fmaf(6.0f, u3, fmaf(-6.0f, u2, 1.5f * u)));
    float fp = fmaf(c, q, fmaf(-1.5f, u2, 1.5f));
    a        = fabsf(fp);
}

__global__ void __launch_bounds__(TPB, 1)
vcl_burgers_kernel(const float* __restrict__ init, float* __restrict__ out) {
    // Double-buffered halo exchange: [buffer][thread]
    __shared__ float s_u0[2][TPB], s_f0[2][TPB], s_a0[2][TPB];  // each thread's FIRST point
    __shared__ float s_u7[2][TPB], s_f7[2][TPB], s_a7[2][TPB];  // each thread's LAST point

    const int row  = blockIdx.x;
    const int tid  = threadIdx.x;
    const int base = tid * PPT;
    const float LAM = (float)(0.002 / (10.0 / 2048.0));  // dt/dx = 0.4096

    float u[PPT];
    {
        const float4* ip = reinterpret_cast<const float4*>(init + (size_t)row * NPTS + base);
        float4 a0 = ip[0];
        float4 a1 = ip[1];
        u[0] = a0.x; u[1] = a0.y; u[2] = a0.z; u[3] = a0.w;
        u[4] = a1.x; u[5] = a1.y; u[6] = a1.z; u[7] = a1.w;
        // frame 0 = init
        float4* op = reinterpret_cast<float4*>(out + (size_t)row * NPTS + base);
        __stcs(op,     a0);
        __stcs(op + 1, a1);
    }

    int p = 0;
    for (int s = 1; s < STEPS; ++s) {
        // 1) flux + wave speed for owned points (computed exactly once per point)
        float f[PPT], a[PPT];
        #pragma unroll
        for (int k = 0; k < PPT; ++k) flux_and_speed(u[k], f[k], a[k]);

        // 2) publish boundary triples, one barrier
        s_u0[p][tid] = u[0];       s_f0[p][tid] = f[0];       s_a0[p][tid] = a[0];
        s_u7[p][tid] = u[PPT-1];   s_f7[p][tid] = f[PPT-1];   s_a7[p][tid] = a[PPT-1];
        __syncthreads();

        float um, fm, am, up, fpn, ap;
        if (tid > 0)       { um = s_u7[p][tid-1]; fm = s_f7[p][tid-1]; am = s_a7[p][tid-1]; }
        else               { um = u[0];           fm = f[0];           am = a[0]; }        // dummy (un[0] overwritten)
        if (tid < TPB - 1) { up = s_u0[p][tid+1]; fpn = s_f0[p][tid+1]; ap = s_a0[p][tid+1]; }
        else               { up = u[PPT-1];       fpn = f[PPT-1];       ap = a[PPT-1]; }   // dummy (un[7] overwritten)

        // extended arrays: index 0 = left halo, 1..PPT = owned, PPT+1 = right halo
        float ve[PPT+2], fe[PPT+2], ae[PPT+2];
        ve[0] = um; fe[0] = fm; ae[0] = am;
        #pragma unroll
        for (int k = 0; k < PPT; ++k) { ve[k+1] = u[k]; fe[k+1] = f[k]; ae[k+1] = a[k]; }
        ve[PPT+1] = up; fe[PPT+1] = fpn; ae[PPT+1] = ap;

        // 3) interfaces fh[i] between ve[i], ve[i+1]  (i = 0..PPT)
        float fh[PPT+1];
        #pragma unroll
        for (int i = 0; i <= PPT; ++i) {
            float al = fmaxf(ae[i], ae[i+1]);
            fh[i] = 0.5f * (fe[i] + fe[i+1]) - 0.5f * al * (ve[i+1] - ve[i]);
        }

        // 4) update owned points; fix outflow boundaries at global edges
        float un[PPT];
        #pragma unroll
        for (int k = 0; k < PPT; ++k)
            un[k] = u[k] - LAM * (fh[k+1] - fh[k]);
        if (tid == 0)       un[0]     = un[1];
        if (tid == TPB - 1) un[PPT-1] = un[PPT-2];

        // 5) stream frame s to global (write-only -> evict-first)
        float4* op = reinterpret_cast<float4*>(out + ((size_t)s * BATCH + row) * NPTS + base);
        __stcs(op,     make_float4(un[0], un[1], un[2], un[3]));
        __stcs(op + 1, make_float4(un[4], un[5], un[6], un[7]));

        #pragma unroll
        for (int k = 0; k < PPT; ++k) u[k] = un[k];
        p ^= 1;
    }
}

extern "C" void kernel_launch(void* const* d_in, const int* in_sizes, int n_in,
                              void* d_out, int out_size) {
    const float* init = (const float*)d_in[0];   // [128, 2048] fp32
    // d_in[1] = stepnum (int32 scalar) -- fixed at 256 by the problem spec
    float* out = (float*)d_out;                  // [256, 128, 2048] fp32
    vcl_burgers_kernel<<<BATCH, TPB>>>(init, out);
}

// round 2
// speedup vs baseline: 1.2027x; 1.2027x over previous
#include <cuda_runtime.h>

// VariantCoeLinear1d: 1D Rusanov FV solver, 128 rows x 2048 pts x 256 steps.
// One persistent CTA per row (128 CTAs = single wave on 148 SMs).
// 256 threads x 8 register-resident points; one __syncthreads per step;
// halo (u, f, |f'|) exchanged via double-buffered float4 SMEM slots.
//
// R2: flux/flux' collapsed to monomial form and evaluated with packed
// fma.rn.f32x2 (2 points per instruction); |f'| via 64-bit AND (ALU pipe);
// 0.5 folded into lambda; float4 halo exchange. Targets the issue-slot
// bound seen in R1 (fma=48.6%, issue=79.8%, dram=29.5%).

#define BATCH 128
#define NPTS  2048
#define STEPS 256
#define TPB   256
#define PPT   8   // TPB*PPT == NPTS

typedef unsigned long long u64;

static __device__ __forceinline__ u64 pk(float lo, float hi) {
    u64 r; asm("mov.b64 %0,{%1,%2};" : "=l"(r) : "f"(lo), "f"(hi)); return r;
}
static __device__ __forceinline__ void upk(float& lo, float& hi, u64 v) {
    asm("mov.b64 {%0,%1},%2;" : "=f"(lo), "=f"(hi) : "l"(v));
}
static __device__ __forceinline__ u64 f2fma(u64 a, u64 b, u64 c) {
    u64 d; asm("fma.rn.f32x2 %0,%1,%2,%3;" : "=l"(d) : "l"(a), "l"(b), "l"(c)); return d;
}
static __device__ __forceinline__ u64 f2mul(u64 a, u64 b) {
    u64 d; asm("mul.rn.f32x2 %0,%1,%2;" : "=l"(d) : "l"(a), "l"(b)); return d;
}

__global__ void __launch_bounds__(TPB, 1)
vcl_kernel(const float* __restrict__ init, float* __restrict__ out)
{
    // double-buffered halo: {u, f, a, pad} for each thread's first/last point
    __shared__ float4 sL[2][TPB];
    __shared__ float4 sR[2][TPB];

    const int row = blockIdx.x;
    const int tid = threadIdx.x;
    const int base = tid * PPT;
    const float HL = 0.5f * (float)(0.002 / (10.0 / 2048.0));  // 0.5*dt/dx

    // flux(u)  = B1 u + B2 u^2 + B3 u^3 + B4 u^4 + B6 u^6
    // flux'(u) = A0 + A1 u + A2 u^2 + A3 u^3 + A5 u^5     (c = beta/12 = 1/120)
    const u64 B1 = pk(1.5f, 1.5f);
    const u64 B2 = pk((float)(0.75 * 0.1 / 12.0),  (float)(0.75 * 0.1 / 12.0));
    const u64 B3 = pk((float)(-0.5 - 2.0 * 0.1 / 12.0), (float)(-0.5 - 2.0 * 0.1 / 12.0));
    const u64 B4 = pk((float)(1.5 * 0.1 / 12.0),   (float)(1.5 * 0.1 / 12.0));
    const u64 B6 = pk((float)(-0.25 * 0.1 / 12.0), (float)(-0.25 * 0.1 / 12.0));
    const u64 A0 = pk(1.5f, 1.5f);
    const u64 A1 = pk((float)(1.5 * 0.1 / 12.0),   (float)(1.5 * 0.1 / 12.0));
    const u64 A2 = pk((float)(-1.5 - 6.0 * 0.1 / 12.0), (float)(-1.5 - 6.0 * 0.1 / 12.0));
    const u64 A3 = pk((float)(6.0 * 0.1 / 12.0),   (float)(6.0 * 0.1 / 12.0));
    const u64 A5 = pk((float)(-1.5 * 0.1 / 12.0),  (float)(-1.5 * 0.1 / 12.0));
    const u64 ABSM = 0x7fffffff7fffffffULL;

    float u[PPT];
    {
        const float4* ip = reinterpret_cast<const float4*>(init + (size_t)row * NPTS + base);
        float4 a0 = ip[0], a1 = ip[1];
        u[0] = a0.x; u[1] = a0.y; u[2] = a0.z; u[3] = a0.w;
        u[4] = a1.x; u[5] = a1.y; u[6] = a1.z; u[7] = a1.w;
        float4* op = reinterpret_cast<float4*>(out + (size_t)row * NPTS + base);
        __stcs(op, a0);
        __stcs(op + 1, a1);
    }

    float4* op = reinterpret_cast<float4*>(out + ((size_t)BATCH + row) * NPTS + base);
    const size_t ostride = (size_t)BATCH * NPTS / 4;   // float4 units per step

    int p = 0;
    #pragma unroll 1
    for (int s = 1; s < STEPS; ++s) {
        // ---- 1) flux + |flux'| for 8 owned points, packed 2-wide ----
        float f[PPT], a[PPT];
        #pragma unroll
        for (int i = 0; i < PPT / 2; ++i) {
            u64 U  = pk(u[2 * i], u[2 * i + 1]);
            u64 u2 = f2mul(U, U);
            u64 u3 = f2mul(u2, U);
            u64 u4 = f2mul(u2, u2);
            u64 u5 = f2mul(u2, u3);
            u64 u6 = f2mul(u3, u3);
            u64 F  = f2fma(B6, u6, f2fma(B4, u4, f2fma(B3, u3, f2fma(B2, u2, f2mul(B1, U)))));
            u64 P  = f2fma(A5, u5, f2fma(A3, u3, f2fma(A2, u2, f2fma(A1, U, A0))));
            u64 A  = P & ABSM;                       // |f'| pairwise (ALU pipe)
            upk(f[2 * i], f[2 * i + 1], F);
            upk(a[2 * i], a[2 * i + 1], A);
        }

        // ---- 2) halo exchange (one barrier) ----
        sL[p][tid] = make_float4(u[0],       f[0],       a[0],       0.0f);
        sR[p][tid] = make_float4(u[PPT - 1], f[PPT - 1], a[PPT - 1], 0.0f);
        __syncthreads();
        // dummy halos at the global edges are fine: those un[] get overwritten by BC
        const int tl = (tid > 0)       ? tid - 1 : 0;
        const int tr = (tid < TPB - 1) ? tid + 1 : TPB - 1;
        float4 nl = sR[p][tl];
        float4 nr = sL[p][tr];

        // ---- 3) interfaces: fh[i] between ext[i] and ext[i+1], i = 0..8 ----
        float ve[PPT + 2], fe[PPT + 2], ae[PPT + 2];
        ve[0] = nl.x; fe[0] = nl.y; ae[0] = nl.z;
        #pragma unroll
        for (int k = 0; k < PPT; ++k) { ve[k + 1] = u[k]; fe[k + 1] = f[k]; ae[k + 1] = a[k]; }
        ve[PPT + 1] = nr.x; fe[PPT + 1] = nr.y; ae[PPT + 1] = nr.z;

        float fh[PPT + 1];
        #pragma unroll
        for (int i = 0; i <= PPT; ++i) {
            float al = fmaxf(ae[i], ae[i + 1]);                 // ALU pipe
            fh[i] = fmaf(-al, ve[i + 1] - ve[i], fe[i] + fe[i + 1]);  // 0.5 folded into HL
        }

        // ---- 4) update + outflow BC ----
        float un[PPT];
        #pragma unroll
        for (int k = 0; k < PPT; ++k)
            un[k] = fmaf(-HL, fh[k + 1] - fh[k], u[k]);
        if (tid == 0)       un[0]       = un[1];
        if (tid == TPB - 1) un[PPT - 1] = un[PPT - 2];

        // ---- 5) stream frame (write-only; evict-first) ----
        __stcs(op,     make_float4(un[0], un[1], un[2], un[3]));
        __stcs(op + 1, make_float4(un[4], un[5], un[6], un[7]));
        op += ostride;

        #pragma unroll
        for (int k = 0; k < PPT; ++k) u[k] = un[k];
        p ^= 1;
    }
}

extern "C" void kernel_launch(void* const* d_in, const int* in_sizes, int n_in,
                              void* d_out, int out_size) {
    const float* init = (const float*)d_in[0];   // [128, 2048] fp32
    // d_in[1] = stepnum (int32) — fixed at 256 by the problem spec
    float* out = (float*)d_out;                  // [256, 128, 2048] fp32
    vcl_kernel<<<BATCH, TPB>>>(init, out);
}